// round 10
// baseline (speedup 1.0000x reference)
#include <cuda_runtime.h>

#define D_MODEL 2048
#define S_LEN   2048
#define N_HEADS 16
#define HD      128

// Scratch (allocation-free rule: __device__ globals)
__device__ __align__(16) float g_Q[S_LEN * D_MODEL];
__device__ __align__(16) float g_K[S_LEN * D_MODEL];
__device__ __align__(16) float g_V[S_LEN * D_MODEL];
__device__ __align__(16) float g_O[S_LEN * D_MODEL];
__device__ __align__(16) float g_Xr[S_LEN * D_MODEL];
__device__ __align__(16) float g_Wq[D_MODEL * D_MODEL];
__device__ __align__(16) float g_Wk[D_MODEL * D_MODEL];
__device__ __align__(16) float g_Wv[D_MODEL * D_MODEL];
__device__ __align__(16) float g_Wo[D_MODEL * D_MODEL];

__device__ __forceinline__ float f2tf(float x) {
    unsigned r;
    asm("cvt.rna.tf32.f32 %0, %1;" : "=r"(r) : "f"(x));
    return __uint_as_float(r);
}

__device__ __forceinline__ void mma_tf32(float* c, const unsigned* a, const unsigned* b) {
    asm volatile(
        "mma.sync.aligned.m16n8k8.row.col.f32.tf32.tf32.f32 "
        "{%0,%1,%2,%3}, {%4,%5,%6,%7}, {%8,%9}, {%0,%1,%2,%3};\n"
        : "+f"(c[0]), "+f"(c[1]), "+f"(c[2]), "+f"(c[3])
        : "r"(a[0]), "r"(a[1]), "r"(a[2]), "r"(a[3]), "r"(b[0]), "r"(b[1]));
}

__device__ __forceinline__ void ldsm4(unsigned* r, const float* p) {
    unsigned addr = (unsigned)__cvta_generic_to_shared(p);
    asm volatile("ldmatrix.sync.aligned.m8n8.x4.shared.b16 {%0,%1,%2,%3}, [%4];"
                 : "=r"(r[0]), "=r"(r[1]), "=r"(r[2]), "=r"(r[3]) : "r"(addr));
}

__device__ __forceinline__ void cpa16(unsigned dst, const void* src) {
    asm volatile("cp.async.cg.shared.global [%0], [%1], 16;" :: "r"(dst), "l"(src));
}
__device__ __forceinline__ void cpa_commit() {
    asm volatile("cp.async.commit_group;");
}
template <int N>
__device__ __forceinline__ void cpa_wait() {
    asm volatile("cp.async.wait_group %0;" :: "n"(N));
}

// ---------------------------------------------------------------------------
// Fused one-shot tf32 rounding of all 5 input tensors (blockIdx.y selects)
// ---------------------------------------------------------------------------
__global__ __launch_bounds__(256)
void round5_k(const float4* __restrict__ x,  float4* __restrict__ xr,
              const float4* __restrict__ wq, float4* __restrict__ wqr,
              const float4* __restrict__ wk, float4* __restrict__ wkr,
              const float4* __restrict__ wv, float4* __restrict__ wvr,
              const float4* __restrict__ wo, float4* __restrict__ wor, int n4)
{
    int i = blockIdx.x * blockDim.x + threadIdx.x;
    if (i >= n4) return;
    const float4* s;
    float4* d;
    switch (blockIdx.y) {
        case 0: s = x;  d = xr;  break;
        case 1: s = wq; d = wqr; break;
        case 2: s = wk; d = wkr; break;
        case 3: s = wv; d = wvr; break;
        default: s = wo; d = wor; break;
    }
    float4 v = s[i];
    d[i] = make_float4(f2tf(v.x), f2tf(v.y), f2tf(v.z), f2tf(v.w));
}

// ---------------------------------------------------------------------------
// C[2048,2048] = A @ B^T, tf32 mma + ldmatrix + 3-stage cp.async pipeline,
// one syncthreads per k-iter, and REGISTER-LEVEL FRAGMENT DOUBLE-BUFFERING:
// fragments for ks+1 are loaded while the 16 mma of ks run dependency-free.
// blockIdx.z selects (B, C) -> fused QKV in one launch.
// 128x128 CTA, BK=32, 8 warps (4m x 2n), warp tile 32x64, smem stride 36.
// ---------------------------------------------------------------------------
#define G_TILE 4608  // 128*36 floats

__global__ __launch_bounds__(256, 2)
void gemm_tf32(const float* __restrict__ A,
               const float* __restrict__ B0, const float* __restrict__ B1,
               const float* __restrict__ B2,
               float* __restrict__ C0, float* __restrict__ C1,
               float* __restrict__ C2, int round_out)
{
    extern __shared__ __align__(16) float smem[];  // 3*2*G_TILE floats

    const float* B = (blockIdx.z == 0) ? B0 : (blockIdx.z == 1) ? B1 : B2;
    float*       C = (blockIdx.z == 0) ? C0 : (blockIdx.z == 1) ? C1 : C2;
    const int K = 2048, N = 2048;

    const int t    = threadIdx.x;
    const int lane = t & 31;
    const int wid  = t >> 5;
    const int wm   = (wid & 3) * 32;
    const int wn   = (wid >> 2) * 64;

    const int la7  = lane & 7;
    const int lb   = (lane >> 3) & 1;
    const int lc   = lane >> 4;
    const int arow = la7 + 8 * lb;
    const int acol = 4 * lc;
    const int brow = la7 + 8 * lc;
    const int bcol = 4 * lb;

    const float* Ab = A + (size_t)(blockIdx.y * 128) * K;
    const float* Bb = B + (size_t)(blockIdx.x * 128) * K;

    const unsigned smem_u = (unsigned)__cvta_generic_to_shared(smem);
    const int ldrow = t >> 3;        // 0..31
    const int ldc4  = (t & 7) << 2;  // 0..28

    float acc[2][8][4];
#pragma unroll
    for (int mt = 0; mt < 2; mt++)
#pragma unroll
        for (int nt = 0; nt < 8; nt++)
#pragma unroll
            for (int r = 0; r < 4; r++) acc[mt][nt][r] = 0.f;

    auto issue = [&](int kt, int st) {
        unsigned as_u = smem_u + (unsigned)(st * 2 * G_TILE) * 4u;
        unsigned bs_u = as_u + (unsigned)G_TILE * 4u;
        const float* Ak = Ab + kt * 32;
        const float* Bk = Bb + kt * 32;
#pragma unroll
        for (int p = 0; p < 4; p++) {
            int row = p * 32 + ldrow;
            cpa16(as_u + (unsigned)(row * 36 + ldc4) * 4u, Ak + (size_t)row * K + ldc4);
            cpa16(bs_u + (unsigned)(row * 36 + ldc4) * 4u, Bk + (size_t)row * K + ldc4);
        }
    };

    // fragment loader for one ks-step (a: 8 regs, b: 16 regs)
    auto ldfrag = [&](const float* As_, const float* Bs_, int kk,
                      unsigned* a, unsigned* b) {
        ldsm4(a,     &As_[(wm + arow)      * 36 + kk + acol]);
        ldsm4(a + 4, &As_[(wm + 16 + arow) * 36 + kk + acol]);
#pragma unroll
        for (int ntp = 0; ntp < 4; ntp++)
            ldsm4(b + 4 * ntp, &Bs_[(wn + ntp * 16 + brow) * 36 + kk + bcol]);
    };
    auto dofma = [&](const unsigned* a, const unsigned* b) {
#pragma unroll
        for (int ntp = 0; ntp < 4; ntp++) {
            mma_tf32(acc[0][2 * ntp],     a,     b + 4 * ntp);
            mma_tf32(acc[0][2 * ntp + 1], a,     b + 4 * ntp + 2);
            mma_tf32(acc[1][2 * ntp],     a + 4, b + 4 * ntp);
            mma_tf32(acc[1][2 * ntp + 1], a + 4, b + 4 * ntp + 2);
        }
    };

    const int nk = K >> 5;  // 64
    issue(0, 0); cpa_commit();
    issue(1, 1); cpa_commit();

    unsigned fa[2][8], fb[2][16];

    int st = 0;
    for (int kt = 0; kt < nk; kt++) {
        cpa_wait<1>();        // group kt arrived (kt+1 may be in flight)
        __syncthreads();      // stage st visible; stage (kt-1)%3 free
        if (kt + 2 < nk) {
            int st2 = st + 2; if (st2 >= 3) st2 -= 3;
            issue(kt + 2, st2);
        }
        cpa_commit();

        const float* As_ = smem + st * 2 * G_TILE;
        const float* Bs_ = As_ + G_TILE;

        // ks-pipelined: load frags ks+1 while mma of ks runs dependency-free
        ldfrag(As_, Bs_, 0, fa[0], fb[0]);
#pragma unroll
        for (int ks = 0; ks < 4; ks++) {
            const int cur = ks & 1;
            if (ks < 3) ldfrag(As_, Bs_, (ks + 1) * 8, fa[cur ^ 1], fb[cur ^ 1]);
            dofma(fa[cur], fb[cur]);
        }
        st++; if (st == 3) st = 0;
    }

    const int gid = lane >> 2, tig = lane & 3;
    const int crow = blockIdx.y * 128 + wm;
    const int ccol = blockIdx.x * 128 + wn;
#pragma unroll
    for (int mt = 0; mt < 2; mt++) {
#pragma unroll
        for (int nt = 0; nt < 8; nt++) {
            int row = crow + mt * 16 + gid;
            int col = ccol + nt * 8 + tig * 2;
            float v0 = acc[mt][nt][0], v1 = acc[mt][nt][1];
            float v2 = acc[mt][nt][2], v3 = acc[mt][nt][3];
            if (round_out) {
                v0 = f2tf(v0); v1 = f2tf(v1); v2 = f2tf(v2); v3 = f2tf(v3);
            }
            *(float2*)(C + (size_t)row * N + col)       = make_float2(v0, v1);
            *(float2*)(C + (size_t)(row + 8) * N + col) = make_float2(v2, v3);
        }
    }
}

// ---------------------------------------------------------------------------
// Flash attention (byte-identical to R8 passing kernel)
// ---------------------------------------------------------------------------
#define Q_STR 132
#define K_STR 132
#define V_STR 136

__global__ __launch_bounds__(128, 2)
void attn_tf32()
{
    extern __shared__ __align__(16) float sm[];
    float* Qs = sm;
    float* Ks = sm + 64 * Q_STR;
    float* Vs = sm + 64 * (Q_STR + K_STR);

    const int t    = threadIdx.x;
    const int lane = t & 31;
    const int wid  = t >> 5;
    const int gid  = lane >> 2;
    const int tig  = lane & 3;
    const int m0   = wid * 16 + gid;
    const int m1   = m0 + 8;

    const int la7  = lane & 7;
    const int lb   = (lane >> 3) & 1;
    const int lc   = lane >> 4;
    const int arow = la7 + 8 * lb;
    const int acol = 4 * lc;
    const int brow = la7 + 8 * lc;
    const int bcol = 4 * lb;

    const int qb = blockIdx.x * 64;
    const size_t hoff = (size_t)blockIdx.y * HD;

    const unsigned smem_u = (unsigned)__cvta_generic_to_shared(sm);
    const unsigned k_u = smem_u + (unsigned)(64 * Q_STR) * 4u;
    const unsigned v_u = smem_u + (unsigned)(64 * (Q_STR + K_STR)) * 4u;

    const int ldrow = t >> 5;
    const int ldc4  = (t & 31) << 2;

    auto issueK = [&](int kb2) {
#pragma unroll
        for (int p = 0; p < 16; p++) {
            int row = p * 4 + ldrow;
            cpa16(k_u + (unsigned)(row * K_STR + ldc4) * 4u,
                  g_K + (size_t)(kb2 + row) * D_MODEL + hoff + ldc4);
        }
    };
    auto issueV = [&](int kb2) {
#pragma unroll
        for (int p = 0; p < 16; p++) {
            int row = p * 4 + ldrow;
            cpa16(v_u + (unsigned)(row * V_STR + ldc4) * 4u,
                  g_V + (size_t)(kb2 + row) * D_MODEL + hoff + ldc4);
        }
    };

    {
#pragma unroll
        for (int p = 0; p < 16; p++) {
            int row = p * 4 + ldrow;
            cpa16(smem_u + (unsigned)(row * Q_STR + ldc4) * 4u,
                  g_Q + (size_t)(qb + row) * D_MODEL + hoff + ldc4);
        }
        cpa_commit();
        issueK(0); cpa_commit();
        issueV(0); cpa_commit();
    }
    cpa_wait<1>();
    __syncthreads();

    float o[16][4];
#pragma unroll
    for (int nt = 0; nt < 16; nt++)
#pragma unroll
        for (int r = 0; r < 4; r++) o[nt][r] = 0.f;
    float mrow0 = -1e30f, mrow1 = -1e30f, lrow0 = 0.f, lrow1 = 0.f;

    const float scale = 0.08838834764831845f;

    for (int kb = 0; kb < S_LEN; kb += 64) {
        float sc[8][4];
#pragma unroll
        for (int nt = 0; nt < 8; nt++)
#pragma unroll
            for (int r = 0; r < 4; r++) sc[nt][r] = 0.f;

#pragma unroll
        for (int ks = 0; ks < 16; ks++) {
            const int kk = ks * 8;
            unsigned a[4];
            ldsm4(a, &Qs[(wid * 16 + arow) * Q_STR + kk + acol]);
#pragma unroll
            for (int ntp = 0; ntp < 4; ntp++) {
                unsigned b[4];
                ldsm4(b, &Ks[(ntp * 16 + brow) * K_STR + kk + bcol]);
                mma_tf32(sc[2 * ntp],     a, b);
                mma_tf32(sc[2 * ntp + 1], a, b + 2);
            }
        }

        float mx0 = -1e30f, mx1 = -1e30f;
#pragma unroll
        for (int nt = 0; nt < 8; nt++) {
            sc[nt][0] *= scale; sc[nt][1] *= scale;
            sc[nt][2] *= scale; sc[nt][3] *= scale;
            mx0 = fmaxf(mx0, fmaxf(sc[nt][0], sc[nt][1]));
            mx1 = fmaxf(mx1, fmaxf(sc[nt][2], sc[nt][3]));
        }
        mx0 = fmaxf(mx0, __shfl_xor_sync(0xffffffffu, mx0, 1));
        mx0 = fmaxf(mx0, __shfl_xor_sync(0xffffffffu, mx0, 2));
        mx1 = fmaxf(mx1, __shfl_xor_sync(0xffffffffu, mx1, 1));
        mx1 = fmaxf(mx1, __shfl_xor_sync(0xffffffffu, mx1, 2));

        float mn0 = fmaxf(mrow0, mx0), mn1 = fmaxf(mrow1, mx1);
        float al0 = __expf(mrow0 - mn0), al1 = __expf(mrow1 - mn1);
        mrow0 = mn0; mrow1 = mn1;

        float sum0 = 0.f, sum1 = 0.f;
#pragma unroll
        for (int nt = 0; nt < 8; nt++) {
            sc[nt][0] = __expf(sc[nt][0] - mn0);
            sc[nt][1] = __expf(sc[nt][1] - mn0);
            sc[nt][2] = __expf(sc[nt][2] - mn1);
            sc[nt][3] = __expf(sc[nt][3] - mn1);
            sum0 += sc[nt][0] + sc[nt][1];
            sum1 += sc[nt][2] + sc[nt][3];
        }
        sum0 += __shfl_xor_sync(0xffffffffu, sum0, 1);
        sum0 += __shfl_xor_sync(0xffffffffu, sum0, 2);
        sum1 += __shfl_xor_sync(0xffffffffu, sum1, 1);
        sum1 += __shfl_xor_sync(0xffffffffu, sum1, 2);
        lrow0 = lrow0 * al0 + sum0;
        lrow1 = lrow1 * al1 + sum1;
#pragma unroll
        for (int nt = 0; nt < 16; nt++) {
            o[nt][0] *= al0; o[nt][1] *= al0;
            o[nt][2] *= al1; o[nt][3] *= al1;
        }

        unsigned pa[8][4];
        {
            const int l1 = (gid << 2) + (tig >> 1);
            const int l2 = l1 + 2;
            const bool e = tig & 1;
#pragma unroll
            for (int ks = 0; ks < 8; ks++) {
                float v0a = __shfl_sync(0xffffffffu, sc[ks][0], l1);
                float v0b = __shfl_sync(0xffffffffu, sc[ks][1], l1);
                float v1a = __shfl_sync(0xffffffffu, sc[ks][2], l1);
                float v1b = __shfl_sync(0xffffffffu, sc[ks][3], l1);
                float v2a = __shfl_sync(0xffffffffu, sc[ks][0], l2);
                float v2b = __shfl_sync(0xffffffffu, sc[ks][1], l2);
                float v3a = __shfl_sync(0xffffffffu, sc[ks][2], l2);
                float v3b = __shfl_sync(0xffffffffu, sc[ks][3], l2);
                pa[ks][0] = __float_as_uint(f2tf(e ? v0b : v0a));
                pa[ks][1] = __float_as_uint(f2tf(e ? v1b : v1a));
                pa[ks][2] = __float_as_uint(f2tf(e ? v2b : v2a));
                pa[ks][3] = __float_as_uint(f2tf(e ? v3b : v3a));
            }
        }

        __syncthreads();
        if (kb + 64 < S_LEN) issueK(kb + 64);
        cpa_commit();
        cpa_wait<1>();
        __syncthreads();

#pragma unroll
        for (int ks = 0; ks < 8; ks++) {
            const int kk = ks * 8;
            const float* vr0 = &Vs[(kk + tig)     * V_STR + gid];
            const float* vr1 = &Vs[(kk + tig + 4) * V_STR + gid];
#pragma unroll
            for (int nt = 0; nt < 16; nt++) {
                unsigned b[2];
                b[0] = __float_as_uint(vr0[nt * 8]);
                b[1] = __float_as_uint(vr1[nt * 8]);
                mma_tf32(o[nt], pa[ks], b);
            }
        }

        __syncthreads();
        if (kb + 64 < S_LEN) issueV(kb + 64);
        cpa_commit();
        cpa_wait<1>();
        __syncthreads();
    }

    float inv0 = 1.f / lrow0, inv1 = 1.f / lrow1;
#pragma unroll
    for (int nt = 0; nt < 16; nt++) {
        int col = nt * 8 + tig * 2;
        float* d0 = g_O + (size_t)(qb + m0) * D_MODEL + hoff + col;
        float* d1 = g_O + (size_t)(qb + m1) * D_MODEL + hoff + col;
        *(float2*)d0 = make_float2(f2tf(o[nt][0] * inv0), f2tf(o[nt][1] * inv0));
        *(float2*)d1 = make_float2(f2tf(o[nt][2] * inv1), f2tf(o[nt][3] * inv1));
    }
}

// ---------------------------------------------------------------------------
extern "C" void kernel_launch(void* const* d_in, const int* in_sizes, int n_in,
                              void* d_out, int out_size)
{
    (void)in_sizes; (void)n_in; (void)out_size;
    const float* x  = (const float*)d_in[0];
    const float* wq = (const float*)d_in[1];
    const float* wk = (const float*)d_in[2];
    const float* wv = (const float*)d_in[3];
    const float* wo = (const float*)d_in[4];
    float* out = (float*)d_out;

    float *Qp, *Kp, *Vp, *Op, *Xr, *Wq, *Wk, *Wv, *Wo;
    cudaGetSymbolAddress((void**)&Qp, g_Q);
    cudaGetSymbolAddress((void**)&Kp, g_K);
    cudaGetSymbolAddress((void**)&Vp, g_V);
    cudaGetSymbolAddress((void**)&Op, g_O);
    cudaGetSymbolAddress((void**)&Xr, g_Xr);
    cudaGetSymbolAddress((void**)&Wq, g_Wq);
    cudaGetSymbolAddress((void**)&Wk, g_Wk);
    cudaGetSymbolAddress((void**)&Wv, g_Wv);
    cudaGetSymbolAddress((void**)&Wo, g_Wo);

    const size_t GEMM_SMEM = (size_t)(3 * 2 * G_TILE) * sizeof(float);  // 110592
    const size_t ATT_SMEM  = (size_t)(64 * (Q_STR + K_STR + V_STR)) * sizeof(float);  // 102400
    cudaFuncSetAttribute(gemm_tf32, cudaFuncAttributeMaxDynamicSharedMemorySize, (int)GEMM_SMEM);
    cudaFuncSetAttribute(attn_tf32, cudaFuncAttributeMaxDynamicSharedMemorySize, (int)ATT_SMEM);

    const int n4 = S_LEN * D_MODEL / 4;
    round5_k<<<dim3(n4 / 256, 5), 256>>>(
        (const float4*)x,  (float4*)Xr,
        (const float4*)wq, (float4*)Wq,
        (const float4*)wk, (float4*)Wk,
        (const float4*)wv, (float4*)Wv,
        (const float4*)wo, (float4*)Wo, n4);

    dim3 gqkv(D_MODEL / 128, S_LEN / 128, 3);  // 16 x 16 x 3
    gemm_tf32<<<gqkv, 256, GEMM_SMEM>>>(Xr, Wq, Wk, Wv, Qp, Kp, Vp, 1);

    attn_tf32<<<dim3(S_LEN / 64, N_HEADS), 128, ATT_SMEM>>>();

    dim3 go(D_MODEL / 128, S_LEN / 128, 1);
    gemm_tf32<<<go, 256, GEMM_SMEM>>>(Op, Wo, Wo, Wo, out, out, out, 0);
}

// round 12
// speedup vs baseline: 1.5474x; 1.5474x over previous
#include <cuda_runtime.h>

#define D_MODEL 2048
#define S_LEN   2048
#define N_HEADS 16
#define HD      128

// Scratch (allocation-free rule: __device__ globals)
__device__ __align__(16) float g_Q[S_LEN * D_MODEL];
__device__ __align__(16) float g_K[S_LEN * D_MODEL];
__device__ __align__(16) float g_V[S_LEN * D_MODEL];
__device__ __align__(16) float g_O[S_LEN * D_MODEL];
__device__ __align__(16) float g_Xr[S_LEN * D_MODEL];
__device__ __align__(16) float g_Wq[D_MODEL * D_MODEL];
__device__ __align__(16) float g_Wk[D_MODEL * D_MODEL];
__device__ __align__(16) float g_Wv[D_MODEL * D_MODEL];
__device__ __align__(16) float g_Wo[D_MODEL * D_MODEL];

__device__ __forceinline__ float f2tf(float x) {
    unsigned r;
    asm("cvt.rna.tf32.f32 %0, %1;" : "=r"(r) : "f"(x));
    return __uint_as_float(r);
}

__device__ __forceinline__ void mma_tf32(float* c, const unsigned* a, const unsigned* b) {
    asm volatile(
        "mma.sync.aligned.m16n8k8.row.col.f32.tf32.tf32.f32 "
        "{%0,%1,%2,%3}, {%4,%5,%6,%7}, {%8,%9}, {%0,%1,%2,%3};\n"
        : "+f"(c[0]), "+f"(c[1]), "+f"(c[2]), "+f"(c[3])
        : "r"(a[0]), "r"(a[1]), "r"(a[2]), "r"(a[3]), "r"(b[0]), "r"(b[1]));
}

__device__ __forceinline__ void ldsm4(unsigned* r, const float* p) {
    unsigned addr = (unsigned)__cvta_generic_to_shared(p);
    asm volatile("ldmatrix.sync.aligned.m8n8.x4.shared.b16 {%0,%1,%2,%3}, [%4];"
                 : "=r"(r[0]), "=r"(r[1]), "=r"(r[2]), "=r"(r[3]) : "r"(addr));
}

__device__ __forceinline__ void cpa16(unsigned dst, const void* src) {
    asm volatile("cp.async.cg.shared.global [%0], [%1], 16;" :: "r"(dst), "l"(src));
}
__device__ __forceinline__ void cpa_commit() {
    asm volatile("cp.async.commit_group;");
}
template <int N>
__device__ __forceinline__ void cpa_wait() {
    asm volatile("cp.async.wait_group %0;" :: "n"(N));
}

// ---------------------------------------------------------------------------
// Fused one-shot tf32 rounding of all 5 input tensors (blockIdx.y selects)
// ---------------------------------------------------------------------------
__global__ __launch_bounds__(256)
void round5_k(const float4* __restrict__ x,  float4* __restrict__ xr,
              const float4* __restrict__ wq, float4* __restrict__ wqr,
              const float4* __restrict__ wk, float4* __restrict__ wkr,
              const float4* __restrict__ wv, float4* __restrict__ wvr,
              const float4* __restrict__ wo, float4* __restrict__ wor, int n4)
{
    int i = blockIdx.x * blockDim.x + threadIdx.x;
    if (i >= n4) return;
    const float4* s;
    float4* d;
    switch (blockIdx.y) {
        case 0: s = x;  d = xr;  break;
        case 1: s = wq; d = wqr; break;
        case 2: s = wk; d = wkr; break;
        case 3: s = wv; d = wvr; break;
        default: s = wo; d = wor; break;
    }
    float4 v = s[i];
    d[i] = make_float4(f2tf(v.x), f2tf(v.y), f2tf(v.z), f2tf(v.w));
}

// ---------------------------------------------------------------------------
// C[2048,2048] = A @ B^T, tf32 mma + ldmatrix + 3-stage cp.async pipeline.
// 4 WARPS, WARP TILE 64x64: 8 ldsm.x4 (32 wavefronts) feed 32 mma per ks-step
// (1.0 wf/mma vs 1.5 in the 8-warp/32x64 layout) -> LSU no longer the cap.
// CTA 128x128, BK=32, smem stride 36, one syncthreads per k-iter,
// issue-before-compute distance 2. blockIdx.z selects (B, C) for fused QKV.
// ---------------------------------------------------------------------------
#define G_TILE 4608  // 128*36 floats

__global__ __launch_bounds__(128, 2)
void gemm_tf32(const float* __restrict__ A,
               const float* __restrict__ B0, const float* __restrict__ B1,
               const float* __restrict__ B2,
               float* __restrict__ C0, float* __restrict__ C1,
               float* __restrict__ C2, int round_out)
{
    extern __shared__ __align__(16) float smem[];  // 3*2*G_TILE floats

    const float* B = (blockIdx.z == 0) ? B0 : (blockIdx.z == 1) ? B1 : B2;
    float*       C = (blockIdx.z == 0) ? C0 : (blockIdx.z == 1) ? C1 : C2;
    const int K = 2048, N = 2048;

    const int t    = threadIdx.x;
    const int lane = t & 31;
    const int wid  = t >> 5;          // 0..3
    const int wm   = (wid & 1) * 64;  // warp m offset
    const int wn   = (wid >> 1) * 64; // warp n offset

    const int la7  = lane & 7;
    const int lb   = (lane >> 3) & 1;
    const int lc   = lane >> 4;
    const int arow = la7 + 8 * lb;
    const int acol = 4 * lc;
    const int brow = la7 + 8 * lc;
    const int bcol = 4 * lb;

    const float* Ab = A + (size_t)(blockIdx.y * 128) * K;
    const float* Bb = B + (size_t)(blockIdx.x * 128) * K;

    const unsigned smem_u = (unsigned)__cvta_generic_to_shared(smem);
    const int ldrow = t >> 3;        // 0..15 (+p*16)
    const int ldc4  = (t & 7) << 2;  // 0..28

    float acc[4][8][4];
#pragma unroll
    for (int mi = 0; mi < 4; mi++)
#pragma unroll
        for (int nj = 0; nj < 8; nj++)
#pragma unroll
            for (int r = 0; r < 4; r++) acc[mi][nj][r] = 0.f;

    auto issue = [&](int kt, int st) {
        unsigned as_u = smem_u + (unsigned)(st * 2 * G_TILE) * 4u;
        unsigned bs_u = as_u + (unsigned)G_TILE * 4u;
        const float* Ak = Ab + kt * 32;
        const float* Bk = Bb + kt * 32;
#pragma unroll
        for (int p = 0; p < 8; p++) {
            int row = p * 16 + ldrow;
            cpa16(as_u + (unsigned)(row * 36 + ldc4) * 4u, Ak + (size_t)row * K + ldc4);
            cpa16(bs_u + (unsigned)(row * 36 + ldc4) * 4u, Bk + (size_t)row * K + ldc4);
        }
    };

    const int nk = K >> 5;  // 64
    issue(0, 0); cpa_commit();
    issue(1, 1); cpa_commit();

    int st = 0;
    for (int kt = 0; kt < nk; kt++) {
        cpa_wait<1>();        // group kt arrived (kt+1 may be in flight)
        __syncthreads();      // stage st visible; stage (kt-1)%3 free
        if (kt + 2 < nk) {
            int st2 = st + 2; if (st2 >= 3) st2 -= 3;
            issue(kt + 2, st2);
        }
        cpa_commit();

        const float* As_ = smem + st * 2 * G_TILE;
        const float* Bs_ = As_ + G_TILE;
#pragma unroll
        for (int ks = 0; ks < 4; ks++) {
            const int kk = ks * 8;
            unsigned a[16], b[16];
#pragma unroll
            for (int i = 0; i < 4; i++)
                ldsm4(a + 4 * i, &As_[(wm + 16 * i + arow) * 36 + kk + acol]);
#pragma unroll
            for (int j = 0; j < 4; j++)
                ldsm4(b + 4 * j, &Bs_[(wn + 16 * j + brow) * 36 + kk + bcol]);
#pragma unroll
            for (int mi = 0; mi < 4; mi++)
#pragma unroll
                for (int bj = 0; bj < 4; bj++) {
                    mma_tf32(acc[mi][2 * bj],     a + 4 * mi, b + 4 * bj);
                    mma_tf32(acc[mi][2 * bj + 1], a + 4 * mi, b + 4 * bj + 2);
                }
        }
        st++; if (st == 3) st = 0;
    }

    const int gid = lane >> 2, tig = lane & 3;
    const int crow = blockIdx.y * 128 + wm;
    const int ccol = blockIdx.x * 128 + wn;
#pragma unroll
    for (int mi = 0; mi < 4; mi++) {
#pragma unroll
        for (int nj = 0; nj < 8; nj++) {
            int row = crow + mi * 16 + gid;
            int col = ccol + nj * 8 + tig * 2;
            float v0 = acc[mi][nj][0], v1 = acc[mi][nj][1];
            float v2 = acc[mi][nj][2], v3 = acc[mi][nj][3];
            if (round_out) {
                v0 = f2tf(v0); v1 = f2tf(v1); v2 = f2tf(v2); v3 = f2tf(v3);
            }
            *(float2*)(C + (size_t)row * N + col)       = make_float2(v0, v1);
            *(float2*)(C + (size_t)(row + 8) * N + col) = make_float2(v2, v3);
        }
    }
}

// ---------------------------------------------------------------------------
// Flash attention (byte-identical to R8 passing kernel)
// ---------------------------------------------------------------------------
#define Q_STR 132
#define K_STR 132
#define V_STR 136

__global__ __launch_bounds__(128, 2)
void attn_tf32()
{
    extern __shared__ __align__(16) float sm[];
    float* Qs = sm;
    float* Ks = sm + 64 * Q_STR;
    float* Vs = sm + 64 * (Q_STR + K_STR);

    const int t    = threadIdx.x;
    const int lane = t & 31;
    const int wid  = t >> 5;
    const int gid  = lane >> 2;
    const int tig  = lane & 3;
    const int m0   = wid * 16 + gid;
    const int m1   = m0 + 8;

    const int la7  = lane & 7;
    const int lb   = (lane >> 3) & 1;
    const int lc   = lane >> 4;
    const int arow = la7 + 8 * lb;
    const int acol = 4 * lc;
    const int brow = la7 + 8 * lc;
    const int bcol = 4 * lb;

    const int qb = blockIdx.x * 64;
    const size_t hoff = (size_t)blockIdx.y * HD;

    const unsigned smem_u = (unsigned)__cvta_generic_to_shared(sm);
    const unsigned k_u = smem_u + (unsigned)(64 * Q_STR) * 4u;
    const unsigned v_u = smem_u + (unsigned)(64 * (Q_STR + K_STR)) * 4u;

    const int ldrow = t >> 5;
    const int ldc4  = (t & 31) << 2;

    auto issueK = [&](int kb2) {
#pragma unroll
        for (int p = 0; p < 16; p++) {
            int row = p * 4 + ldrow;
            cpa16(k_u + (unsigned)(row * K_STR + ldc4) * 4u,
                  g_K + (size_t)(kb2 + row) * D_MODEL + hoff + ldc4);
        }
    };
    auto issueV = [&](int kb2) {
#pragma unroll
        for (int p = 0; p < 16; p++) {
            int row = p * 4 + ldrow;
            cpa16(v_u + (unsigned)(row * V_STR + ldc4) * 4u,
                  g_V + (size_t)(kb2 + row) * D_MODEL + hoff + ldc4);
        }
    };

    {
#pragma unroll
        for (int p = 0; p < 16; p++) {
            int row = p * 4 + ldrow;
            cpa16(smem_u + (unsigned)(row * Q_STR + ldc4) * 4u,
                  g_Q + (size_t)(qb + row) * D_MODEL + hoff + ldc4);
        }
        cpa_commit();
        issueK(0); cpa_commit();
        issueV(0); cpa_commit();
    }
    cpa_wait<1>();
    __syncthreads();

    float o[16][4];
#pragma unroll
    for (int nt = 0; nt < 16; nt++)
#pragma unroll
        for (int r = 0; r < 4; r++) o[nt][r] = 0.f;
    float mrow0 = -1e30f, mrow1 = -1e30f, lrow0 = 0.f, lrow1 = 0.f;

    const float scale = 0.08838834764831845f;

    for (int kb = 0; kb < S_LEN; kb += 64) {
        float sc[8][4];
#pragma unroll
        for (int nt = 0; nt < 8; nt++)
#pragma unroll
            for (int r = 0; r < 4; r++) sc[nt][r] = 0.f;

#pragma unroll
        for (int ks = 0; ks < 16; ks++) {
            const int kk = ks * 8;
            unsigned a[4];
            ldsm4(a, &Qs[(wid * 16 + arow) * Q_STR + kk + acol]);
#pragma unroll
            for (int ntp = 0; ntp < 4; ntp++) {
                unsigned b[4];
                ldsm4(b, &Ks[(ntp * 16 + brow) * K_STR + kk + bcol]);
                mma_tf32(sc[2 * ntp],     a, b);
                mma_tf32(sc[2 * ntp + 1], a, b + 2);
            }
        }

        float mx0 = -1e30f, mx1 = -1e30f;
#pragma unroll
        for (int nt = 0; nt < 8; nt++) {
            sc[nt][0] *= scale; sc[nt][1] *= scale;
            sc[nt][2] *= scale; sc[nt][3] *= scale;
            mx0 = fmaxf(mx0, fmaxf(sc[nt][0], sc[nt][1]));
            mx1 = fmaxf(mx1, fmaxf(sc[nt][2], sc[nt][3]));
        }
        mx0 = fmaxf(mx0, __shfl_xor_sync(0xffffffffu, mx0, 1));
        mx0 = fmaxf(mx0, __shfl_xor_sync(0xffffffffu, mx0, 2));
        mx1 = fmaxf(mx1, __shfl_xor_sync(0xffffffffu, mx1, 1));
        mx1 = fmaxf(mx1, __shfl_xor_sync(0xffffffffu, mx1, 2));

        float mn0 = fmaxf(mrow0, mx0), mn1 = fmaxf(mrow1, mx1);
        float al0 = __expf(mrow0 - mn0), al1 = __expf(mrow1 - mn1);
        mrow0 = mn0; mrow1 = mn1;

        float sum0 = 0.f, sum1 = 0.f;
#pragma unroll
        for (int nt = 0; nt < 8; nt++) {
            sc[nt][0] = __expf(sc[nt][0] - mn0);
            sc[nt][1] = __expf(sc[nt][1] - mn0);
            sc[nt][2] = __expf(sc[nt][2] - mn1);
            sc[nt][3] = __expf(sc[nt][3] - mn1);
            sum0 += sc[nt][0] + sc[nt][1];
            sum1 += sc[nt][2] + sc[nt][3];
        }
        sum0 += __shfl_xor_sync(0xffffffffu, sum0, 1);
        sum0 += __shfl_xor_sync(0xffffffffu, sum0, 2);
        sum1 += __shfl_xor_sync(0xffffffffu, sum1, 1);
        sum1 += __shfl_xor_sync(0xffffffffu, sum1, 2);
        lrow0 = lrow0 * al0 + sum0;
        lrow1 = lrow1 * al1 + sum1;
#pragma unroll
        for (int nt = 0; nt < 16; nt++) {
            o[nt][0] *= al0; o[nt][1] *= al0;
            o[nt][2] *= al1; o[nt][3] *= al1;
        }

        unsigned pa[8][4];
        {
            const int l1 = (gid << 2) + (tig >> 1);
            const int l2 = l1 + 2;
            const bool e = tig & 1;
#pragma unroll
            for (int ks = 0; ks < 8; ks++) {
                float v0a = __shfl_sync(0xffffffffu, sc[ks][0], l1);
                float v0b = __shfl_sync(0xffffffffu, sc[ks][1], l1);
                float v1a = __shfl_sync(0xffffffffu, sc[ks][2], l1);
                float v1b = __shfl_sync(0xffffffffu, sc[ks][3], l1);
                float v2a = __shfl_sync(0xffffffffu, sc[ks][0], l2);
                float v2b = __shfl_sync(0xffffffffu, sc[ks][1], l2);
                float v3a = __shfl_sync(0xffffffffu, sc[ks][2], l2);
                float v3b = __shfl_sync(0xffffffffu, sc[ks][3], l2);
                pa[ks][0] = __float_as_uint(f2tf(e ? v0b : v0a));
                pa[ks][1] = __float_as_uint(f2tf(e ? v1b : v1a));
                pa[ks][2] = __float_as_uint(f2tf(e ? v2b : v2a));
                pa[ks][3] = __float_as_uint(f2tf(e ? v3b : v3a));
            }
        }

        __syncthreads();
        if (kb + 64 < S_LEN) issueK(kb + 64);
        cpa_commit();
        cpa_wait<1>();
        __syncthreads();

#pragma unroll
        for (int ks = 0; ks < 8; ks++) {
            const int kk = ks * 8;
            const float* vr0 = &Vs[(kk + tig)     * V_STR + gid];
            const float* vr1 = &Vs[(kk + tig + 4) * V_STR + gid];
#pragma unroll
            for (int nt = 0; nt < 16; nt++) {
                unsigned b[2];
                b[0] = __float_as_uint(vr0[nt * 8]);
                b[1] = __float_as_uint(vr1[nt * 8]);
                mma_tf32(o[nt], pa[ks], b);
            }
        }

        __syncthreads();
        if (kb + 64 < S_LEN) issueV(kb + 64);
        cpa_commit();
        cpa_wait<1>();
        __syncthreads();
    }

    float inv0 = 1.f / lrow0, inv1 = 1.f / lrow1;
#pragma unroll
    for (int nt = 0; nt < 16; nt++) {
        int col = nt * 8 + tig * 2;
        float* d0 = g_O + (size_t)(qb + m0) * D_MODEL + hoff + col;
        float* d1 = g_O + (size_t)(qb + m1) * D_MODEL + hoff + col;
        *(float2*)d0 = make_float2(f2tf(o[nt][0] * inv0), f2tf(o[nt][1] * inv0));
        *(float2*)d1 = make_float2(f2tf(o[nt][2] * inv1), f2tf(o[nt][3] * inv1));
    }
}

// ---------------------------------------------------------------------------
extern "C" void kernel_launch(void* const* d_in, const int* in_sizes, int n_in,
                              void* d_out, int out_size)
{
    (void)in_sizes; (void)n_in; (void)out_size;
    const float* x  = (const float*)d_in[0];
    const float* wq = (const float*)d_in[1];
    const float* wk = (const float*)d_in[2];
    const float* wv = (const float*)d_in[3];
    const float* wo = (const float*)d_in[4];
    float* out = (float*)d_out;

    float *Qp, *Kp, *Vp, *Op, *Xr, *Wq, *Wk, *Wv, *Wo;
    cudaGetSymbolAddress((void**)&Qp, g_Q);
    cudaGetSymbolAddress((void**)&Kp, g_K);
    cudaGetSymbolAddress((void**)&Vp, g_V);
    cudaGetSymbolAddress((void**)&Op, g_O);
    cudaGetSymbolAddress((void**)&Xr, g_Xr);
    cudaGetSymbolAddress((void**)&Wq, g_Wq);
    cudaGetSymbolAddress((void**)&Wk, g_Wk);
    cudaGetSymbolAddress((void**)&Wv, g_Wv);
    cudaGetSymbolAddress((void**)&Wo, g_Wo);

    const size_t GEMM_SMEM = (size_t)(3 * 2 * G_TILE) * sizeof(float);  // 110592
    const size_t ATT_SMEM  = (size_t)(64 * (Q_STR + K_STR + V_STR)) * sizeof(float);  // 102400
    cudaFuncSetAttribute(gemm_tf32, cudaFuncAttributeMaxDynamicSharedMemorySize, (int)GEMM_SMEM);
    cudaFuncSetAttribute(attn_tf32, cudaFuncAttributeMaxDynamicSharedMemorySize, (int)ATT_SMEM);

    const int n4 = S_LEN * D_MODEL / 4;
    round5_k<<<dim3(n4 / 256, 5), 256>>>(
        (const float4*)x,  (float4*)Xr,
        (const float4*)wq, (float4*)Wq,
        (const float4*)wk, (float4*)Wk,
        (const float4*)wv, (float4*)Wv,
        (const float4*)wo, (float4*)Wo, n4);

    dim3 gqkv(D_MODEL / 128, S_LEN / 128, 3);  // 16 x 16 x 3
    gemm_tf32<<<gqkv, 128, GEMM_SMEM>>>(Xr, Wq, Wk, Wv, Qp, Kp, Vp, 1);

    attn_tf32<<<dim3(S_LEN / 64, N_HEADS), 128, ATT_SMEM>>>();

    dim3 go(D_MODEL / 128, S_LEN / 128, 1);
    gemm_tf32<<<go, 128, GEMM_SMEM>>>(Op, Wo, Wo, Wo, out, out, out, 0);
}

// round 14
// speedup vs baseline: 2.9734x; 1.9216x over previous
#include <cuda_runtime.h>
#include <cuda_fp16.h>

#define D_MODEL 2048
#define S_LEN   2048
#define N_HEADS 16
#define HD      128

// Scratch (allocation-free rule: __device__ globals) — all fp16 now
__device__ __align__(16) __half g_Q[S_LEN * D_MODEL];
__device__ __align__(16) __half g_K[S_LEN * D_MODEL];
__device__ __align__(16) __half g_V[S_LEN * D_MODEL];
__device__ __align__(16) __half g_O[S_LEN * D_MODEL];
__device__ __align__(16) __half g_Xh[S_LEN * D_MODEL];
__device__ __align__(16) __half g_Wq[D_MODEL * D_MODEL];
__device__ __align__(16) __half g_Wk[D_MODEL * D_MODEL];
__device__ __align__(16) __half g_Wv[D_MODEL * D_MODEL];
__device__ __align__(16) __half g_Wo[D_MODEL * D_MODEL];

// fp16 m16n8k16, fp32 accumulate
__device__ __forceinline__ void mma_f16(float* c, const unsigned* a, const unsigned* b) {
    asm volatile(
        "mma.sync.aligned.m16n8k16.row.col.f32.f16.f16.f32 "
        "{%0,%1,%2,%3}, {%4,%5,%6,%7}, {%8,%9}, {%0,%1,%2,%3};\n"
        : "+f"(c[0]), "+f"(c[1]), "+f"(c[2]), "+f"(c[3])
        : "r"(a[0]), "r"(a[1]), "r"(a[2]), "r"(a[3]), "r"(b[0]), "r"(b[1]));
}

__device__ __forceinline__ void ldsm4(unsigned* r, const __half* p) {
    unsigned addr = (unsigned)__cvta_generic_to_shared(p);
    asm volatile("ldmatrix.sync.aligned.m8n8.x4.shared.b16 {%0,%1,%2,%3}, [%4];"
                 : "=r"(r[0]), "=r"(r[1]), "=r"(r[2]), "=r"(r[3]) : "r"(addr));
}
__device__ __forceinline__ void ldsm4t(unsigned* r, const __half* p) {
    unsigned addr = (unsigned)__cvta_generic_to_shared(p);
    asm volatile("ldmatrix.sync.aligned.m8n8.x4.trans.shared.b16 {%0,%1,%2,%3}, [%4];"
                 : "=r"(r[0]), "=r"(r[1]), "=r"(r[2]), "=r"(r[3]) : "r"(addr));
}

__device__ __forceinline__ void cpa16(unsigned dst, const void* src) {
    asm volatile("cp.async.cg.shared.global [%0], [%1], 16;" :: "r"(dst), "l"(src));
}
__device__ __forceinline__ void cpa_commit() {
    asm volatile("cp.async.commit_group;");
}
template <int N>
__device__ __forceinline__ void cpa_wait() {
    asm volatile("cp.async.wait_group %0;" :: "n"(N));
}

__device__ __forceinline__ unsigned packh2(float lo, float hi) {
    __half2 h = __floats2half2_rn(lo, hi);   // lo -> .x (low half)
    return *(unsigned*)&h;
}

// ---------------------------------------------------------------------------
// Fused fp32 -> fp16 conversion of all 5 input tensors (blockIdx.y selects)
// ---------------------------------------------------------------------------
__global__ __launch_bounds__(256)
void cvt5_k(const float4* __restrict__ x,  __half2* __restrict__ xr,
            const float4* __restrict__ wq, __half2* __restrict__ wqr,
            const float4* __restrict__ wk, __half2* __restrict__ wkr,
            const float4* __restrict__ wv, __half2* __restrict__ wvr,
            const float4* __restrict__ wo, __half2* __restrict__ wor, int n4)
{
    int i = blockIdx.x * blockDim.x + threadIdx.x;
    if (i >= n4) return;
    const float4* s;
    __half2* d;
    switch (blockIdx.y) {
        case 0: s = x;  d = xr;  break;
        case 1: s = wq; d = wqr; break;
        case 2: s = wk; d = wkr; break;
        case 3: s = wv; d = wvr; break;
        default: s = wo; d = wor; break;
    }
    float4 v = s[i];
    d[2 * i]     = __floats2half2_rn(v.x, v.y);
    d[2 * i + 1] = __floats2half2_rn(v.z, v.w);
}

// ---------------------------------------------------------------------------
// C[2048,2048] = A @ B^T, fp16 m16n8k16 mma + ldmatrix + 3-stage cp.async.
// A,B fp16 (K-contiguous). CTA 128x128, BK=64 halves (128 B/row), 4 warps,
// warp tile 64x64. smem stride 72 halves (=36 words, %32==4: conflict-free
// ldmatrix phases). One syncthreads/k-iter, prefetch distance 2.
// blockIdx.z selects (B, C) for fused QKV. C: fp16 (QKV) or fp32 (final).
// ---------------------------------------------------------------------------
#define GSTR    72
#define G_HALF  (128 * GSTR)           // halves per matrix per stage (9216)

__global__ __launch_bounds__(128, 2)
void gemm_f16(const __half* __restrict__ A,
              const __half* __restrict__ B0, const __half* __restrict__ B1,
              const __half* __restrict__ B2,
              void* __restrict__ C0, void* __restrict__ C1,
              void* __restrict__ C2, int half_out)
{
    extern __shared__ __align__(16) __half hsm[];   // 3 stages x 2 x G_HALF

    const __half* B = (blockIdx.z == 0) ? B0 : (blockIdx.z == 1) ? B1 : B2;
    void*         C = (blockIdx.z == 0) ? C0 : (blockIdx.z == 1) ? C1 : C2;
    const int K = 2048, N = 2048;

    const int t    = threadIdx.x;
    const int lane = t & 31;
    const int wid  = t >> 5;          // 0..3
    const int wm   = (wid & 1) * 64;
    const int wn   = (wid >> 1) * 64;

    const int la7  = lane & 7;
    const int lb   = (lane >> 3) & 1;
    const int lc   = lane >> 4;
    const int arow = la7 + 8 * lb;    // A: 16 rows, k +8*lc
    const int acol = 8 * lc;
    const int brow = la7 + 8 * lc;    // B: 16 rows, k +8*lb
    const int bcol = 8 * lb;

    const __half* Ab = A + (size_t)(blockIdx.y * 128) * K;
    const __half* Bb = B + (size_t)(blockIdx.x * 128) * K;

    const unsigned smem_u = (unsigned)__cvta_generic_to_shared(hsm);
    const int ldrow = t >> 3;         // 0..15 (+p*16)
    const int ldch  = (t & 7) << 3;   // half offset 0..56

    float acc[4][8][4];
#pragma unroll
    for (int mi = 0; mi < 4; mi++)
#pragma unroll
        for (int nj = 0; nj < 8; nj++)
#pragma unroll
            for (int r = 0; r < 4; r++) acc[mi][nj][r] = 0.f;

    auto issue = [&](int kt, int st) {
        unsigned as_u = smem_u + (unsigned)(st * 2 * G_HALF) * 2u;
        unsigned bs_u = as_u + (unsigned)G_HALF * 2u;
        const __half* Ak = Ab + kt * 64;
        const __half* Bk = Bb + kt * 64;
#pragma unroll
        for (int p = 0; p < 8; p++) {
            int row = p * 16 + ldrow;
            cpa16(as_u + (unsigned)(row * GSTR + ldch) * 2u, Ak + (size_t)row * K + ldch);
            cpa16(bs_u + (unsigned)(row * GSTR + ldch) * 2u, Bk + (size_t)row * K + ldch);
        }
    };

    const int nk = K >> 6;  // 32
    issue(0, 0); cpa_commit();
    issue(1, 1); cpa_commit();

    int st = 0;
    for (int kt = 0; kt < nk; kt++) {
        cpa_wait<1>();
        __syncthreads();
        if (kt + 2 < nk) {
            int st2 = st + 2; if (st2 >= 3) st2 -= 3;
            issue(kt + 2, st2);
        }
        cpa_commit();

        const __half* As_ = hsm + st * 2 * G_HALF;
        const __half* Bs_ = As_ + G_HALF;
#pragma unroll
        for (int ks = 0; ks < 4; ks++) {         // k16 steps over BK=64
            const int kk = ks * 16;
            unsigned a[16], b[16];
#pragma unroll
            for (int i = 0; i < 4; i++)
                ldsm4(a + 4 * i, &As_[(wm + 16 * i + arow) * GSTR + kk + acol]);
#pragma unroll
            for (int j = 0; j < 4; j++)
                ldsm4(b + 4 * j, &Bs_[(wn + 16 * j + brow) * GSTR + kk + bcol]);
#pragma unroll
            for (int mi = 0; mi < 4; mi++)
#pragma unroll
                for (int j = 0; j < 4; j++) {
                    mma_f16(acc[mi][2 * j],     a + 4 * mi, b + 4 * j);
                    mma_f16(acc[mi][2 * j + 1], a + 4 * mi, b + 4 * j + 2);
                }
        }
        st++; if (st == 3) st = 0;
    }

    const int gid = lane >> 2, tig = lane & 3;
    const int crow = blockIdx.y * 128 + wm;
    const int ccol = blockIdx.x * 128 + wn;
#pragma unroll
    for (int mi = 0; mi < 4; mi++) {
#pragma unroll
        for (int nj = 0; nj < 8; nj++) {
            int row = crow + mi * 16 + gid;
            int col = ccol + nj * 8 + tig * 2;
            if (half_out) {
                __half* Ch = (__half*)C;
                *(unsigned*)(Ch + (size_t)row * N + col) =
                    packh2(acc[mi][nj][0], acc[mi][nj][1]);
                *(unsigned*)(Ch + (size_t)(row + 8) * N + col) =
                    packh2(acc[mi][nj][2], acc[mi][nj][3]);
            } else {
                float* Cf = (float*)C;
                *(float2*)(Cf + (size_t)row * N + col) =
                    make_float2(acc[mi][nj][0], acc[mi][nj][1]);
                *(float2*)(Cf + (size_t)(row + 8) * N + col) =
                    make_float2(acc[mi][nj][2], acc[mi][nj][3]);
            }
        }
    }
}

// ---------------------------------------------------------------------------
// Flash attention, fp16 m16n8k16. Grid (S/64, H), 128 threads.
// Q/K/V tiles 64x128 halves, stride 136 halves (68 words %32==4, ldmatrix-ok).
// S c-frags convert DIRECTLY to PV a-frags (identity lane mapping) — no
// shuffles, no P smem. V consumed via ldmatrix.x4.trans.
// smem: 3 x 64*136 halves = 52224 B.
// ---------------------------------------------------------------------------
#define ASTR 136

__global__ __launch_bounds__(128, 2)
void attn_f16()
{
    extern __shared__ __align__(16) __half asm_[];
    __half* Qs = asm_;
    __half* Ks = asm_ + 64 * ASTR;
    __half* Vs = asm_ + 2 * 64 * ASTR;

    const int t    = threadIdx.x;
    const int lane = t & 31;
    const int wid  = t >> 5;
    const int gid  = lane >> 2;
    const int tig  = lane & 3;
    const int m0   = wid * 16 + gid;
    const int m1   = m0 + 8;

    const int la7  = lane & 7;
    const int lb   = (lane >> 3) & 1;
    const int lc   = lane >> 4;
    const int arow = la7 + 8 * lb;
    const int acol = 8 * lc;
    const int brow = la7 + 8 * lc;
    const int bcol = 8 * lb;

    const int qb = blockIdx.x * 64;
    const size_t hoff = (size_t)blockIdx.y * HD;

    const unsigned smem_u = (unsigned)__cvta_generic_to_shared(asm_);
    const unsigned k_u = smem_u + (unsigned)(64 * ASTR) * 2u;
    const unsigned v_u = smem_u + (unsigned)(2 * 64 * ASTR) * 2u;

    const int ldrow = t >> 4;         // 0..7 (+p*8)
    const int ldch  = (t & 15) << 3;  // 0..120 halves

    auto issueK = [&](int kb2) {
#pragma unroll
        for (int p = 0; p < 8; p++) {
            int row = p * 8 + ldrow;
            cpa16(k_u + (unsigned)(row * ASTR + ldch) * 2u,
                  g_K + (size_t)(kb2 + row) * D_MODEL + hoff + ldch);
        }
    };
    auto issueV = [&](int kb2) {
#pragma unroll
        for (int p = 0; p < 8; p++) {
            int row = p * 8 + ldrow;
            cpa16(v_u + (unsigned)(row * ASTR + ldch) * 2u,
                  g_V + (size_t)(kb2 + row) * D_MODEL + hoff + ldch);
        }
    };

    {
#pragma unroll
        for (int p = 0; p < 8; p++) {
            int row = p * 8 + ldrow;
            cpa16(smem_u + (unsigned)(row * ASTR + ldch) * 2u,
                  g_Q + (size_t)(qb + row) * D_MODEL + hoff + ldch);
        }
        cpa_commit();
        issueK(0); cpa_commit();
        issueV(0); cpa_commit();
    }
    cpa_wait<1>();   // Q + K0 ready
    __syncthreads();

    float o[16][4];
#pragma unroll
    for (int nt = 0; nt < 16; nt++)
#pragma unroll
        for (int r = 0; r < 4; r++) o[nt][r] = 0.f;
    float mrow0 = -1e30f, mrow1 = -1e30f, lrow0 = 0.f, lrow1 = 0.f;

    const float scale = 0.08838834764831845f;  // 1/sqrt(128)

    for (int kb = 0; kb < S_LEN; kb += 64) {
        // ---- S = Q K^T : 16x64 per warp, 8 k16-steps over hd=128 ----
        float sc[8][4];
#pragma unroll
        for (int nt = 0; nt < 8; nt++)
#pragma unroll
            for (int r = 0; r < 4; r++) sc[nt][r] = 0.f;

#pragma unroll
        for (int ks = 0; ks < 8; ks++) {
            const int kk = ks * 16;
            unsigned a[4];
            ldsm4(a, &Qs[(wid * 16 + arow) * ASTR + kk + acol]);
#pragma unroll
            for (int j = 0; j < 4; j++) {
                unsigned b[4];
                ldsm4(b, &Ks[(16 * j + brow) * ASTR + kk + bcol]);
                mma_f16(sc[2 * j],     a, b);
                mma_f16(sc[2 * j + 1], a, b + 2);
            }
        }

        // ---- Online softmax (rows m0: sc[][0..1], m1: sc[][2..3]) ----
        float mx0 = -1e30f, mx1 = -1e30f;
#pragma unroll
        for (int nt = 0; nt < 8; nt++) {
            sc[nt][0] *= scale; sc[nt][1] *= scale;
            sc[nt][2] *= scale; sc[nt][3] *= scale;
            mx0 = fmaxf(mx0, fmaxf(sc[nt][0], sc[nt][1]));
            mx1 = fmaxf(mx1, fmaxf(sc[nt][2], sc[nt][3]));
        }
        mx0 = fmaxf(mx0, __shfl_xor_sync(0xffffffffu, mx0, 1));
        mx0 = fmaxf(mx0, __shfl_xor_sync(0xffffffffu, mx0, 2));
        mx1 = fmaxf(mx1, __shfl_xor_sync(0xffffffffu, mx1, 1));
        mx1 = fmaxf(mx1, __shfl_xor_sync(0xffffffffu, mx1, 2));

        float mn0 = fmaxf(mrow0, mx0), mn1 = fmaxf(mrow1, mx1);
        float al0 = __expf(mrow0 - mn0), al1 = __expf(mrow1 - mn1);
        mrow0 = mn0; mrow1 = mn1;

        float sum0 = 0.f, sum1 = 0.f;
#pragma unroll
        for (int nt = 0; nt < 8; nt++) {
            sc[nt][0] = __expf(sc[nt][0] - mn0);
            sc[nt][1] = __expf(sc[nt][1] - mn0);
            sc[nt][2] = __expf(sc[nt][2] - mn1);
            sc[nt][3] = __expf(sc[nt][3] - mn1);
            sum0 += sc[nt][0] + sc[nt][1];
            sum1 += sc[nt][2] + sc[nt][3];
        }
        sum0 += __shfl_xor_sync(0xffffffffu, sum0, 1);
        sum0 += __shfl_xor_sync(0xffffffffu, sum0, 2);
        sum1 += __shfl_xor_sync(0xffffffffu, sum1, 1);
        sum1 += __shfl_xor_sync(0xffffffffu, sum1, 2);
        lrow0 = lrow0 * al0 + sum0;
        lrow1 = lrow1 * al1 + sum1;
#pragma unroll
        for (int nt = 0; nt < 16; nt++) {
            o[nt][0] *= al0; o[nt][1] *= al0;
            o[nt][2] *= al1; o[nt][3] *= al1;
        }

        // ---- S c-frags -> PV a-frags: IDENTITY lane mapping, pack to fp16 ----
        unsigned pa[4][4];
#pragma unroll
        for (int ks = 0; ks < 4; ks++) {
            pa[ks][0] = packh2(sc[2 * ks][0],     sc[2 * ks][1]);
            pa[ks][1] = packh2(sc[2 * ks][2],     sc[2 * ks][3]);
            pa[ks][2] = packh2(sc[2 * ks + 1][0], sc[2 * ks + 1][1]);
            pa[ks][3] = packh2(sc[2 * ks + 1][2], sc[2 * ks + 1][3]);
        }

        __syncthreads();                       // all warps done reading Ks
        if (kb + 64 < S_LEN) issueK(kb + 64);  // K[i+1] overlaps PV
        cpa_commit();
        cpa_wait<1>();                         // V[i] arrived
        __syncthreads();

        // ---- O += P @ V : 4 k16-steps over 64 keys, 16 hd-tiles ----
#pragma unroll
        for (int ks = 0; ks < 4; ks++) {
            const int kk = ks * 16;
#pragma unroll
            for (int j2 = 0; j2 < 8; j2++) {
                unsigned bv[4];
                ldsm4t(bv, &Vs[(kk + la7 + 8 * lb) * ASTR + 16 * j2 + 8 * lc]);
                mma_f16(o[2 * j2],     pa[ks], bv);
                mma_f16(o[2 * j2 + 1], pa[ks], bv + 2);
            }
        }

        __syncthreads();                       // all warps done reading Vs
        if (kb + 64 < S_LEN) issueV(kb + 64);  // V[i+1] overlaps next QK
        cpa_commit();
        cpa_wait<1>();                         // K[i+1] arrived
        __syncthreads();
    }

    // Normalize, convert to fp16, write O
    float inv0 = 1.f / lrow0, inv1 = 1.f / lrow1;
#pragma unroll
    for (int nt = 0; nt < 16; nt++) {
        int col = nt * 8 + tig * 2;
        __half* d0 = g_O + (size_t)(qb + m0) * D_MODEL + hoff + col;
        __half* d1 = g_O + (size_t)(qb + m1) * D_MODEL + hoff + col;
        *(unsigned*)d0 = packh2(o[nt][0] * inv0, o[nt][1] * inv0);
        *(unsigned*)d1 = packh2(o[nt][2] * inv1, o[nt][3] * inv1);
    }
}

// ---------------------------------------------------------------------------
extern "C" void kernel_launch(void* const* d_in, const int* in_sizes, int n_in,
                              void* d_out, int out_size)
{
    (void)in_sizes; (void)n_in; (void)out_size;
    const float* x  = (const float*)d_in[0];
    const float* wq = (const float*)d_in[1];
    const float* wk = (const float*)d_in[2];
    const float* wv = (const float*)d_in[3];
    const float* wo = (const float*)d_in[4];
    float* out = (float*)d_out;

    __half *Qp, *Kp, *Vp, *Op, *Xh, *Wq, *Wk, *Wv, *Wo;
    cudaGetSymbolAddress((void**)&Qp, g_Q);
    cudaGetSymbolAddress((void**)&Kp, g_K);
    cudaGetSymbolAddress((void**)&Vp, g_V);
    cudaGetSymbolAddress((void**)&Op, g_O);
    cudaGetSymbolAddress((void**)&Xh, g_Xh);
    cudaGetSymbolAddress((void**)&Wq, g_Wq);
    cudaGetSymbolAddress((void**)&Wk, g_Wk);
    cudaGetSymbolAddress((void**)&Wv, g_Wv);
    cudaGetSymbolAddress((void**)&Wo, g_Wo);

    const size_t GEMM_SMEM = (size_t)(3 * 2 * G_HALF) * sizeof(__half);   // 110592
    const size_t ATT_SMEM  = (size_t)(3 * 64 * ASTR) * sizeof(__half);    // 52224
    cudaFuncSetAttribute(gemm_f16, cudaFuncAttributeMaxDynamicSharedMemorySize, (int)GEMM_SMEM);
    cudaFuncSetAttribute(attn_f16, cudaFuncAttributeMaxDynamicSharedMemorySize, (int)ATT_SMEM);

    // Fused fp32 -> fp16 conversion of all 5 GEMM inputs
    const int n4 = S_LEN * D_MODEL / 4;
    cvt5_k<<<dim3(n4 / 256, 5), 256>>>(
        (const float4*)x,  (__half2*)Xh,
        (const float4*)wq, (__half2*)Wq,
        (const float4*)wk, (__half2*)Wk,
        (const float4*)wv, (__half2*)Wv,
        (const float4*)wo, (__half2*)Wo, n4);

    // Fused QKV projection (blockIdx.z selects weight/output), fp16 out
    dim3 gqkv(D_MODEL / 128, S_LEN / 128, 3);  // 16 x 16 x 3
    gemm_f16<<<gqkv, 128, GEMM_SMEM>>>(Xh, Wq, Wk, Wv, Qp, Kp, Vp, 1);

    attn_f16<<<dim3(S_LEN / 64, N_HEADS), 128, ATT_SMEM>>>();

    // Output projection, fp32 out
    dim3 go(D_MODEL / 128, S_LEN / 128, 1);
    gemm_f16<<<go, 128, GEMM_SMEM>>>(Op, Wo, Wo, Wo, out, out, out, 0);
}

// round 17
// speedup vs baseline: 3.0033x; 1.0101x over previous
#include <cuda_runtime.h>
#include <cuda_fp16.h>

#define D_MODEL 2048
#define S_LEN   2048
#define N_HEADS 16
#define HD      128

// Scratch (allocation-free rule: __device__ globals) — all fp16
__device__ __align__(16) __half g_Q[S_LEN * D_MODEL];
__device__ __align__(16) __half g_K[S_LEN * D_MODEL];
__device__ __align__(16) __half g_V[S_LEN * D_MODEL];
__device__ __align__(16) __half g_O[S_LEN * D_MODEL];
__device__ __align__(16) __half g_Xh[S_LEN * D_MODEL];
__device__ __align__(16) __half g_Wq[D_MODEL * D_MODEL];
__device__ __align__(16) __half g_Wk[D_MODEL * D_MODEL];
__device__ __align__(16) __half g_Wv[D_MODEL * D_MODEL];
__device__ __align__(16) __half g_Wo[D_MODEL * D_MODEL];

// fp16 m16n8k16, fp32 accumulate
__device__ __forceinline__ void mma_f16(float* c, const unsigned* a, const unsigned* b) {
    asm volatile(
        "mma.sync.aligned.m16n8k16.row.col.f32.f16.f16.f32 "
        "{%0,%1,%2,%3}, {%4,%5,%6,%7}, {%8,%9}, {%0,%1,%2,%3};\n"
        : "+f"(c[0]), "+f"(c[1]), "+f"(c[2]), "+f"(c[3])
        : "r"(a[0]), "r"(a[1]), "r"(a[2]), "r"(a[3]), "r"(b[0]), "r"(b[1]));
}

__device__ __forceinline__ void ldsm4(unsigned* r, const __half* p) {
    unsigned addr = (unsigned)__cvta_generic_to_shared(p);
    asm volatile("ldmatrix.sync.aligned.m8n8.x4.shared.b16 {%0,%1,%2,%3}, [%4];"
                 : "=r"(r[0]), "=r"(r[1]), "=r"(r[2]), "=r"(r[3]) : "r"(addr));
}
__device__ __forceinline__ void ldsm4t(unsigned* r, const __half* p) {
    unsigned addr = (unsigned)__cvta_generic_to_shared(p);
    asm volatile("ldmatrix.sync.aligned.m8n8.x4.trans.shared.b16 {%0,%1,%2,%3}, [%4];"
                 : "=r"(r[0]), "=r"(r[1]), "=r"(r[2]), "=r"(r[3]) : "r"(addr));
}

__device__ __forceinline__ void cpa16(unsigned dst, const void* src) {
    asm volatile("cp.async.cg.shared.global [%0], [%1], 16;" :: "r"(dst), "l"(src));
}
__device__ __forceinline__ void cpa_commit() {
    asm volatile("cp.async.commit_group;");
}
template <int N>
__device__ __forceinline__ void cpa_wait() {
    asm volatile("cp.async.wait_group %0;" :: "n"(N));
}

__device__ __forceinline__ unsigned packh2(float lo, float hi) {
    __half2 h = __floats2half2_rn(lo, hi);   // lo -> .x (low half)
    return *(unsigned*)&h;
}

// ---------------------------------------------------------------------------
// Fused fp32 -> fp16 conversion, 4x ILP per thread (MLP=4 to cover DRAM
// latency; was latency-bound at 1 float4/thread). blockIdx.y selects tensor.
// ---------------------------------------------------------------------------
__global__ __launch_bounds__(256)
void cvt5_k(const float4* __restrict__ x,  __half2* __restrict__ xr,
            const float4* __restrict__ wq, __half2* __restrict__ wqr,
            const float4* __restrict__ wk, __half2* __restrict__ wkr,
            const float4* __restrict__ wv, __half2* __restrict__ wvr,
            const float4* __restrict__ wo, __half2* __restrict__ wor, int n4)
{
    const float4* s;
    __half2* d;
    switch (blockIdx.y) {
        case 0: s = x;  d = xr;  break;
        case 1: s = wq; d = wqr; break;
        case 2: s = wk; d = wkr; break;
        case 3: s = wv; d = wvr; break;
        default: s = wo; d = wor; break;
    }
    int base = blockIdx.x * 1024 + threadIdx.x;
    float4 v[4];
#pragma unroll
    for (int u = 0; u < 4; u++) {
        int i = base + u * 256;
        if (i < n4) v[u] = s[i];
    }
#pragma unroll
    for (int u = 0; u < 4; u++) {
        int i = base + u * 256;
        if (i < n4) {
            d[2 * i]     = __floats2half2_rn(v[u].x, v[u].y);
            d[2 * i + 1] = __floats2half2_rn(v[u].z, v[u].w);
        }
    }
}

// ---------------------------------------------------------------------------
// C[2048,2048] = A @ B^T, fp16 m16n8k16 mma + ldmatrix + 3-stage cp.async.
// (Byte-identical to R14 passing kernel — at the mma.sync roofline.)
// ---------------------------------------------------------------------------
#define GSTR    72
#define G_HALF  (128 * GSTR)

__global__ __launch_bounds__(128, 2)
void gemm_f16(const __half* __restrict__ A,
              const __half* __restrict__ B0, const __half* __restrict__ B1,
              const __half* __restrict__ B2,
              void* __restrict__ C0, void* __restrict__ C1,
              void* __restrict__ C2, int half_out)
{
    extern __shared__ __align__(16) __half hsm[];

    const __half* B = (blockIdx.z == 0) ? B0 : (blockIdx.z == 1) ? B1 : B2;
    void*         C = (blockIdx.z == 0) ? C0 : (blockIdx.z == 1) ? C1 : C2;
    const int K = 2048, N = 2048;

    const int t    = threadIdx.x;
    const int lane = t & 31;
    const int wid  = t >> 5;
    const int wm   = (wid & 1) * 64;
    const int wn   = (wid >> 1) * 64;

    const int la7  = lane & 7;
    const int lb   = (lane >> 3) & 1;
    const int lc   = lane >> 4;
    const int arow = la7 + 8 * lb;
    const int acol = 8 * lc;
    const int brow = la7 + 8 * lc;
    const int bcol = 8 * lb;

    const __half* Ab = A + (size_t)(blockIdx.y * 128) * K;
    const __half* Bb = B + (size_t)(blockIdx.x * 128) * K;

    const unsigned smem_u = (unsigned)__cvta_generic_to_shared(hsm);
    const int ldrow = t >> 3;
    const int ldch  = (t & 7) << 3;

    float acc[4][8][4];
#pragma unroll
    for (int mi = 0; mi < 4; mi++)
#pragma unroll
        for (int nj = 0; nj < 8; nj++)
#pragma unroll
            for (int r = 0; r < 4; r++) acc[mi][nj][r] = 0.f;

    auto issue = [&](int kt, int st) {
        unsigned as_u = smem_u + (unsigned)(st * 2 * G_HALF) * 2u;
        unsigned bs_u = as_u + (unsigned)G_HALF * 2u;
        const __half* Ak = Ab + kt * 64;
        const __half* Bk = Bb + kt * 64;
#pragma unroll
        for (int p = 0; p < 8; p++) {
            int row = p * 16 + ldrow;
            cpa16(as_u + (unsigned)(row * GSTR + ldch) * 2u, Ak + (size_t)row * K + ldch);
            cpa16(bs_u + (unsigned)(row * GSTR + ldch) * 2u, Bk + (size_t)row * K + ldch);
        }
    };

    const int nk = K >> 6;  // 32
    issue(0, 0); cpa_commit();
    issue(1, 1); cpa_commit();

    int st = 0;
    for (int kt = 0; kt < nk; kt++) {
        cpa_wait<1>();
        __syncthreads();
        if (kt + 2 < nk) {
            int st2 = st + 2; if (st2 >= 3) st2 -= 3;
            issue(kt + 2, st2);
        }
        cpa_commit();

        const __half* As_ = hsm + st * 2 * G_HALF;
        const __half* Bs_ = As_ + G_HALF;
#pragma unroll
        for (int ks = 0; ks < 4; ks++) {
            const int kk = ks * 16;
            unsigned a[16], b[16];
#pragma unroll
            for (int i = 0; i < 4; i++)
                ldsm4(a + 4 * i, &As_[(wm + 16 * i + arow) * GSTR + kk + acol]);
#pragma unroll
            for (int j = 0; j < 4; j++)
                ldsm4(b + 4 * j, &Bs_[(wn + 16 * j + brow) * GSTR + kk + bcol]);
#pragma unroll
            for (int mi = 0; mi < 4; mi++)
#pragma unroll
                for (int j = 0; j < 4; j++) {
                    mma_f16(acc[mi][2 * j],     a + 4 * mi, b + 4 * j);
                    mma_f16(acc[mi][2 * j + 1], a + 4 * mi, b + 4 * j + 2);
                }
        }
        st++; if (st == 3) st = 0;
    }

    const int gid = lane >> 2, tig = lane & 3;
    const int crow = blockIdx.y * 128 + wm;
    const int ccol = blockIdx.x * 128 + wn;
#pragma unroll
    for (int mi = 0; mi < 4; mi++) {
#pragma unroll
        for (int nj = 0; nj < 8; nj++) {
            int row = crow + mi * 16 + gid;
            int col = ccol + nj * 8 + tig * 2;
            if (half_out) {
                __half* Ch = (__half*)C;
                *(unsigned*)(Ch + (size_t)row * N + col) =
                    packh2(acc[mi][nj][0], acc[mi][nj][1]);
                *(unsigned*)(Ch + (size_t)(row + 8) * N + col) =
                    packh2(acc[mi][nj][2], acc[mi][nj][3]);
            } else {
                float* Cf = (float*)C;
                *(float2*)(Cf + (size_t)row * N + col) =
                    make_float2(acc[mi][nj][0], acc[mi][nj][1]);
                *(float2*)(Cf + (size_t)(row + 8) * N + col) =
                    make_float2(acc[mi][nj][2], acc[mi][nj][3]);
            }
        }
    }
}

// ---------------------------------------------------------------------------
// Flash attention, fp16 m16n8k16. Same body as R14; occupancy raised to
// 3 CTAs/SM (smem 3x52224=157KB < 227KB; reg cap 170) to shrink wave tail:
// 512 CTAs: 1.73 waves @2/SM -> 1.15 @3/SM.
// ---------------------------------------------------------------------------
#define ASTR 136

__global__ __launch_bounds__(128, 3)
void attn_f16()
{
    extern __shared__ __align__(16) __half asm_[];
    __half* Qs = asm_;
    __half* Ks = asm_ + 64 * ASTR;
    __half* Vs = asm_ + 2 * 64 * ASTR;

    const int t    = threadIdx.x;
    const int lane = t & 31;
    const int wid  = t >> 5;
    const int gid  = lane >> 2;
    const int tig  = lane & 3;
    const int m0   = wid * 16 + gid;
    const int m1   = m0 + 8;

    const int la7  = lane & 7;
    const int lb   = (lane >> 3) & 1;
    const int lc   = lane >> 4;
    const int arow = la7 + 8 * lb;
    const int acol = 8 * lc;
    const int brow = la7 + 8 * lc;
    const int bcol = 8 * lb;

    const int qb = blockIdx.x * 64;
    const size_t hoff = (size_t)blockIdx.y * HD;

    const unsigned smem_u = (unsigned)__cvta_generic_to_shared(asm_);
    const unsigned k_u = smem_u + (unsigned)(64 * ASTR) * 2u;
    const unsigned v_u = smem_u + (unsigned)(2 * 64 * ASTR) * 2u;

    const int ldrow = t >> 4;
    const int ldch  = (t & 15) << 3;

    auto issueK = [&](int kb2) {
#pragma unroll
        for (int p = 0; p < 8; p++) {
            int row = p * 8 + ldrow;
            cpa16(k_u + (unsigned)(row * ASTR + ldch) * 2u,
                  g_K + (size_t)(kb2 + row) * D_MODEL + hoff + ldch);
        }
    };
    auto issueV = [&](int kb2) {
#pragma unroll
        for (int p = 0; p < 8; p++) {
            int row = p * 8 + ldrow;
            cpa16(v_u + (unsigned)(row * ASTR + ldch) * 2u,
                  g_V + (size_t)(kb2 + row) * D_MODEL + hoff + ldch);
        }
    };

    {
#pragma unroll
        for (int p = 0; p < 8; p++) {
            int row = p * 8 + ldrow;
            cpa16(smem_u + (unsigned)(row * ASTR + ldch) * 2u,
                  g_Q + (size_t)(qb + row) * D_MODEL + hoff + ldch);
        }
        cpa_commit();
        issueK(0); cpa_commit();
        issueV(0); cpa_commit();
    }
    cpa_wait<1>();
    __syncthreads();

    float o[16][4];
#pragma unroll
    for (int nt = 0; nt < 16; nt++)
#pragma unroll
        for (int r = 0; r < 4; r++) o[nt][r] = 0.f;
    float mrow0 = -1e30f, mrow1 = -1e30f, lrow0 = 0.f, lrow1 = 0.f;

    const float scale = 0.08838834764831845f;

    for (int kb = 0; kb < S_LEN; kb += 64) {
        float sc[8][4];
#pragma unroll
        for (int nt = 0; nt < 8; nt++)
#pragma unroll
            for (int r = 0; r < 4; r++) sc[nt][r] = 0.f;

#pragma unroll
        for (int ks = 0; ks < 8; ks++) {
            const int kk = ks * 16;
            unsigned a[4];
            ldsm4(a, &Qs[(wid * 16 + arow) * ASTR + kk + acol]);
#pragma unroll
            for (int j = 0; j < 4; j++) {
                unsigned b[4];
                ldsm4(b, &Ks[(16 * j + brow) * ASTR + kk + bcol]);
                mma_f16(sc[2 * j],     a, b);
                mma_f16(sc[2 * j + 1], a, b + 2);
            }
        }

        float mx0 = -1e30f, mx1 = -1e30f;
#pragma unroll
        for (int nt = 0; nt < 8; nt++) {
            sc[nt][0] *= scale; sc[nt][1] *= scale;
            sc[nt][2] *= scale; sc[nt][3] *= scale;
            mx0 = fmaxf(mx0, fmaxf(sc[nt][0], sc[nt][1]));
            mx1 = fmaxf(mx1, fmaxf(sc[nt][2], sc[nt][3]));
        }
        mx0 = fmaxf(mx0, __shfl_xor_sync(0xffffffffu, mx0, 1));
        mx0 = fmaxf(mx0, __shfl_xor_sync(0xffffffffu, mx0, 2));
        mx1 = fmaxf(mx1, __shfl_xor_sync(0xffffffffu, mx1, 1));
        mx1 = fmaxf(mx1, __shfl_xor_sync(0xffffffffu, mx1, 2));

        float mn0 = fmaxf(mrow0, mx0), mn1 = fmaxf(mrow1, mx1);
        float al0 = __expf(mrow0 - mn0), al1 = __expf(mrow1 - mn1);
        mrow0 = mn0; mrow1 = mn1;

        float sum0 = 0.f, sum1 = 0.f;
#pragma unroll
        for (int nt = 0; nt < 8; nt++) {
            sc[nt][0] = __expf(sc[nt][0] - mn0);
            sc[nt][1] = __expf(sc[nt][1] - mn0);
            sc[nt][2] = __expf(sc[nt][2] - mn1);
            sc[nt][3] = __expf(sc[nt][3] - mn1);
            sum0 += sc[nt][0] + sc[nt][1];
            sum1 += sc[nt][2] + sc[nt][3];
        }
        sum0 += __shfl_xor_sync(0xffffffffu, sum0, 1);
        sum0 += __shfl_xor_sync(0xffffffffu, sum0, 2);
        sum1 += __shfl_xor_sync(0xffffffffu, sum1, 1);
        sum1 += __shfl_xor_sync(0xffffffffu, sum1, 2);
        lrow0 = lrow0 * al0 + sum0;
        lrow1 = lrow1 * al1 + sum1;
#pragma unroll
        for (int nt = 0; nt < 16; nt++) {
            o[nt][0] *= al0; o[nt][1] *= al0;
            o[nt][2] *= al1; o[nt][3] *= al1;
        }

        unsigned pa[4][4];
#pragma unroll
        for (int ks = 0; ks < 4; ks++) {
            pa[ks][0] = packh2(sc[2 * ks][0],     sc[2 * ks][1]);
            pa[ks][1] = packh2(sc[2 * ks][2],     sc[2 * ks][3]);
            pa[ks][2] = packh2(sc[2 * ks + 1][0], sc[2 * ks + 1][1]);
            pa[ks][3] = packh2(sc[2 * ks + 1][2], sc[2 * ks + 1][3]);
        }

        __syncthreads();
        if (kb + 64 < S_LEN) issueK(kb + 64);
        cpa_commit();
        cpa_wait<1>();
        __syncthreads();

#pragma unroll
        for (int ks = 0; ks < 4; ks++) {
            const int kk = ks * 16;
#pragma unroll
            for (int j2 = 0; j2 < 8; j2++) {
                unsigned bv[4];
                ldsm4t(bv, &Vs[(kk + la7 + 8 * lb) * ASTR + 16 * j2 + 8 * lc]);
                mma_f16(o[2 * j2],     pa[ks], bv);
                mma_f16(o[2 * j2 + 1], pa[ks], bv + 2);
            }
        }

        __syncthreads();
        if (kb + 64 < S_LEN) issueV(kb + 64);
        cpa_commit();
        cpa_wait<1>();
        __syncthreads();
    }

    float inv0 = 1.f / lrow0, inv1 = 1.f / lrow1;
#pragma unroll
    for (int nt = 0; nt < 16; nt++) {
        int col = nt * 8 + tig * 2;
        __half* d0 = g_O + (size_t)(qb + m0) * D_MODEL + hoff + col;
        __half* d1 = g_O + (size_t)(qb + m1) * D_MODEL + hoff + col;
        *(unsigned*)d0 = packh2(o[nt][0] * inv0, o[nt][1] * inv0);
        *(unsigned*)d1 = packh2(o[nt][2] * inv1, o[nt][3] * inv1);
    }
}

// ---------------------------------------------------------------------------
extern "C" void kernel_launch(void* const* d_in, const int* in_sizes, int n_in,
                              void* d_out, int out_size)
{
    (void)in_sizes; (void)n_in; (void)out_size;
    const float* x  = (const float*)d_in[0];
    const float* wq = (const float*)d_in[1];
    const float* wk = (const float*)d_in[2];
    const float* wv = (const float*)d_in[3];
    const float* wo = (const float*)d_in[4];
    float* out = (float*)d_out;

    __half *Qp, *Kp, *Vp, *Op, *Xh, *Wq, *Wk, *Wv, *Wo;
    cudaGetSymbolAddress((void**)&Qp, g_Q);
    cudaGetSymbolAddress((void**)&Kp, g_K);
    cudaGetSymbolAddress((void**)&Vp, g_V);
    cudaGetSymbolAddress((void**)&Op, g_O);
    cudaGetSymbolAddress((void**)&Xh, g_Xh);
    cudaGetSymbolAddress((void**)&Wq, g_Wq);
    cudaGetSymbolAddress((void**)&Wk, g_Wk);
    cudaGetSymbolAddress((void**)&Wv, g_Wv);
    cudaGetSymbolAddress((void**)&Wo, g_Wo);

    const size_t GEMM_SMEM = (size_t)(3 * 2 * G_HALF) * sizeof(__half);   // 110592
    const size_t ATT_SMEM  = (size_t)(3 * 64 * ASTR) * sizeof(__half);    // 52224
    cudaFuncSetAttribute(gemm_f16, cudaFuncAttributeMaxDynamicSharedMemorySize, (int)GEMM_SMEM);
    cudaFuncSetAttribute(attn_f16, cudaFuncAttributeMaxDynamicSharedMemorySize, (int)ATT_SMEM);

    // Fused fp32 -> fp16 conversion, 4x ILP
    const int n4 = S_LEN * D_MODEL / 4;             // 1048576
    cvt5_k<<<dim3(n4 / 1024, 5), 256>>>(
        (const float4*)x,  (__half2*)Xh,
        (const float4*)wq, (__half2*)Wq,
        (const float4*)wk, (__half2*)Wk,
        (const float4*)wv, (__half2*)Wv,
        (const float4*)wo, (__half2*)Wo, n4);

    // Fused QKV projection (blockIdx.z selects weight/output), fp16 out
    dim3 gqkv(D_MODEL / 128, S_LEN / 128, 3);  // 16 x 16 x 3
    gemm_f16<<<gqkv, 128, GEMM_SMEM>>>(Xh, Wq, Wk, Wv, Qp, Kp, Vp, 1);

    attn_f16<<<dim3(S_LEN / 64, N_HEADS), 128, ATT_SMEM>>>();

    // Output projection, fp32 out
    dim3 go(D_MODEL / 128, S_LEN / 128, 1);
    gemm_f16<<<go, 128, GEMM_SMEM>>>(Op, Wo, Wo, Wo, out, out, out, 0);
}